// round 16
// baseline (speedup 1.0000x reference)
#include <cuda_runtime.h>
#include <cuda_bf16.h>
#include <cstdint>

// dist[i,j] = ||s_i||^2 + ||t_j||^2 - 2 <s_i, t_j>
// s: [n, 64] fp32, t: [q, 64] fp32, out: [n, q] fp32. n = q = 16384.
// bf16 mma.m16n8k16 + ldmatrix. Persistent CTAs (2/SM) with a double-buffered
// cp.async.bulk pipeline over 128x256 tiles. t rows stored permuted in gmem
// (bit-swap within 32-row blocks) so the accumulator layout is already
// output-coalesced; straight STG.128 epilogue, no shuffles.

#define D    64
#define BM   128
#define BN   256
#define MAXNQ 16384
#define BUF_BYTES (BM * D * 2 + BN * D * 2)   // 49152 per stage

__device__ float g_s_sq[MAXNQ];
__device__ float g_t_sq[MAXNQ];
// Pre-swizzled bf16 tiles: within each 128B row, 16B chunk c stored at c^(row&7).
__device__ __nv_bfloat16 g_s_bf[MAXNQ * D];
__device__ __nv_bfloat16 g_t_bf[MAXNQ * D];   // rows permuted within 32-blocks

// Involutive bit-swap within a 32-row block: fields (b4,b3) <-> (b2,b1).
__host__ __device__ __forceinline__ int perm32(int p) {
    return (((p >> 2) & 1) << 4) | (((p >> 1) & 1) << 3) |
           (((p >> 4) & 1) << 2) | (((p >> 3) & 1) << 1) | (p & 1);
}

// ---------------- prep: fp32 -> pre-swizzled bf16 + row norms ----------------
__global__ void prep_kernel(const float* __restrict__ s,
                            const float* __restrict__ t, int n, int q) {
    const float* src = blockIdx.y ? t : s;
    __nv_bfloat16* dstb = blockIdx.y ? g_t_bf : g_s_bf;
    float* dstn = blockIdx.y ? g_t_sq : g_s_sq;
    const int lim = blockIdx.y ? q : n;
    const int row = blockIdx.x * 64 + (threadIdx.x >> 2);
    const int part = threadIdx.x & 3;
    if (row >= lim) return;
    const int drow = blockIdx.y ? ((row & ~31) | perm32(row & 31)) : row;
    const float4* p = reinterpret_cast<const float4*>(src + (size_t)row * D) + part * 4;
    float acc = 0.f;
    uint4* rowq = reinterpret_cast<uint4*>(dstb + (size_t)drow * D);
    const int sw = drow & 7;
#pragma unroll
    for (int j = 0; j < 2; j++) {
        float4 a = p[2 * j], b = p[2 * j + 1];
        acc += a.x * a.x + a.y * a.y + a.z * a.z + a.w * a.w;
        acc += b.x * b.x + b.y * b.y + b.z * b.z + b.w * b.w;
        __nv_bfloat162 h0 = __float22bfloat162_rn(make_float2(a.x, a.y));
        __nv_bfloat162 h1 = __float22bfloat162_rn(make_float2(a.z, a.w));
        __nv_bfloat162 h2 = __float22bfloat162_rn(make_float2(b.x, b.y));
        __nv_bfloat162 h3 = __float22bfloat162_rn(make_float2(b.z, b.w));
        uint4 u;
        u.x = *reinterpret_cast<uint32_t*>(&h0);
        u.y = *reinterpret_cast<uint32_t*>(&h1);
        u.z = *reinterpret_cast<uint32_t*>(&h2);
        u.w = *reinterpret_cast<uint32_t*>(&h3);
        rowq[(part * 2 + j) ^ sw] = u;
    }
    acc += __shfl_xor_sync(0xFFFFFFFF, acc, 1);
    acc += __shfl_xor_sync(0xFFFFFFFF, acc, 2);
    if (part == 0) dstn[row] = acc;      // norms in PHYSICAL order
}

// ---------------- helpers ----------------
__device__ __forceinline__ void ldsm_x4(uint32_t& r0, uint32_t& r1,
                                        uint32_t& r2, uint32_t& r3,
                                        uint32_t addr) {
    asm volatile("ldmatrix.sync.aligned.m8n8.x4.shared.b16 {%0,%1,%2,%3}, [%4];"
                 : "=r"(r0), "=r"(r1), "=r"(r2), "=r"(r3) : "r"(addr));
}

__device__ __forceinline__ void mma_bf16(float c[4], const uint32_t a[4],
                                         uint32_t b0, uint32_t b1) {
    asm volatile(
        "mma.sync.aligned.m16n8k16.row.col.f32.bf16.bf16.f32 "
        "{%0,%1,%2,%3}, {%4,%5,%6,%7}, {%8,%9}, {%0,%1,%2,%3};"
        : "+f"(c[0]), "+f"(c[1]), "+f"(c[2]), "+f"(c[3])
        : "r"(a[0]), "r"(a[1]), "r"(a[2]), "r"(a[3]), "r"(b0), "r"(b1));
}

__device__ __forceinline__ void bulk_cp(uint32_t dst, const void* src,
                                        uint32_t bytes, uint32_t mbar) {
    asm volatile(
        "cp.async.bulk.shared::cluster.global.mbarrier::complete_tx::bytes "
        "[%0], [%1], %2, [%3];"
        :: "r"(dst), "l"(src), "r"(bytes), "r"(mbar) : "memory");
}

__device__ __forceinline__ void mbar_wait(uint32_t mb, uint32_t ph) {
    uint32_t done;
    asm volatile(
        "{\n\t.reg .pred p;\n\t"
        "mbarrier.try_wait.parity.acquire.cta.shared::cta.b64 p, [%1], %2;\n\t"
        "selp.b32 %0, 1, 0, p;\n\t}"
        : "=r"(done) : "r"(mb), "r"(ph) : "memory");
    if (!done) {
        asm volatile(
            "{\n\t.reg .pred P1;\n\t"
            "WL_%=:\n\t"
            "mbarrier.try_wait.parity.acquire.cta.shared::cta.b64 P1, [%0], %1, 0x989680;\n\t"
            "@P1 bra.uni WD_%=;\n\tbra.uni WL_%=;\n\tWD_%=:\n\t}"
            :: "r"(mb), "r"(ph) : "memory");
    }
}

// Persistent: grid = min(tiles, 296) CTAs, each loops over tiles with stride.
__global__ __launch_bounds__(256, 2)
void dist_bf16_kernel(float* __restrict__ out, int n, int q, int ncta) {
    extern __shared__ __align__(128) char smem[];
    __shared__ __align__(8) uint64_t mb_full[2];

    const int tid  = threadIdx.x;
    const int lane = tid & 31;
    const int warp = tid >> 5;
    const int wm   = warp >> 2;      // 0..1
    const int wn   = warp & 3;       // 0..3
    const int g    = lane >> 2;      // 0..7
    const int i4   = lane & 3;       // 0..3

    const int tilesX = q / BN;
    const int tiles  = (n / BM) * tilesX;

    const uint32_t sbase = (uint32_t)__cvta_generic_to_shared(smem);
    const uint32_t mbf0  = (uint32_t)__cvta_generic_to_shared(&mb_full[0]);

    if (tid == 0) {
        asm volatile("mbarrier.init.shared.b64 [%0], 1;" :: "r"(mbf0) : "memory");
        asm volatile("mbarrier.init.shared.b64 [%0], 1;" :: "r"(mbf0 + 8) : "memory");
    }
    __syncthreads();

    const int t0 = blockIdx.x;
    if (t0 >= tiles) return;

    // Prologue: DMA tile t0 into buffer 0.
    if (tid == 0) {
        const int rb = (t0 / tilesX) * BM;
        const int cb = (t0 % tilesX) * BN;
        asm volatile("mbarrier.arrive.expect_tx.shared.b64 _, [%0], %1;"
                     :: "r"(mbf0), "r"((uint32_t)BUF_BYTES) : "memory");
        bulk_cp(sbase, g_s_bf + ((size_t)rb << 6), BM * D * 2, mbf0);
        bulk_cp(sbase + BM * D * 2, g_t_bf + ((size_t)cb << 6), BN * D * 2, mbf0);
    }

    const int mrow = wm * 64;
    const int aRow  = mrow + (lane & 15);
    const int aXor  = lane & 7;
    const int kAdd  = lane >> 4;
    const int bRowL = (lane & 7) + ((lane >> 3) & 1) * 8;

    int k = 0;
    for (int tile = t0; tile < tiles; tile += ncta, k++) {
        const int buf = k & 1;
        const int ph  = (k >> 1) & 1;
        const uint32_t sS_base = sbase + buf * BUF_BYTES;
        const uint32_t sT_base = sS_base + BM * D * 2;

        const int rowBase = (tile / tilesX) * BM;
        const int colBase = (tile % tilesX) * BN;

        // Prefetch next tile into the other buffer (its readers finished at
        // the __syncthreads ending iteration k-1).
        const int nxt = tile + ncta;
        if (tid == 0 && nxt < tiles) {
            const uint32_t mbn = mbf0 + 8 * (buf ^ 1);
            const int rb = (nxt / tilesX) * BM;
            const int cb = (nxt % tilesX) * BN;
            asm volatile("mbarrier.arrive.expect_tx.shared.b64 _, [%0], %1;"
                         :: "r"(mbn), "r"((uint32_t)BUF_BYTES) : "memory");
            const uint32_t nb_base = sbase + (buf ^ 1) * BUF_BYTES;
            bulk_cp(nb_base, g_s_bf + ((size_t)rb << 6), BM * D * 2, mbn);
            bulk_cp(nb_base + BM * D * 2, g_t_bf + ((size_t)cb << 6), BN * D * 2, mbn);
        }

        mbar_wait(mbf0 + 8 * buf, ph);

#pragma unroll 1
        for (int nb = 0; nb < 2; nb++) {
            const int ncol = nb * 128 + wn * 32;

            float acc[4][4][4];
#pragma unroll
            for (int a = 0; a < 4; a++)
#pragma unroll
                for (int b = 0; b < 4; b++)
#pragma unroll
                    for (int c = 0; c < 4; c++) acc[a][b][c] = 0.f;

#pragma unroll
            for (int ks = 0; ks < 4; ks++) {
                const int k2 = ks * 2;
                uint32_t a[4][4];
#pragma unroll
                for (int mb2 = 0; mb2 < 4; mb2++) {
                    const int row = aRow + mb2 * 16;
                    const uint32_t addr =
                        sS_base + (uint32_t)(row * 8 + ((k2 + kAdd) ^ aXor)) * 16;
                    ldsm_x4(a[mb2][0], a[mb2][1], a[mb2][2], a[mb2][3], addr);
                }
                uint32_t b[2][4];
#pragma unroll
                for (int nk = 0; nk < 2; nk++) {
                    const int trow = ncol + nk * 16 + bRowL;
                    const uint32_t addr =
                        sT_base + (uint32_t)(trow * 8 + ((k2 + kAdd) ^ (trow & 7))) * 16;
                    ldsm_x4(b[nk][0], b[nk][1], b[nk][2], b[nk][3], addr);
                }
#pragma unroll
                for (int mb2 = 0; mb2 < 4; mb2++)
#pragma unroll
                    for (int nk = 0; nk < 2; nk++) {
                        mma_bf16(acc[mb2][nk * 2 + 0], a[mb2], b[nk][0], b[nk][2]);
                        mma_bf16(acc[mb2][nk * 2 + 1], a[mb2], b[nk][1], b[nk][3]);
                    }
            }

            // ---- Epilogue: coalesced accs; norms via L2-resident LDG ----
            const float4 tn0 = *reinterpret_cast<const float4*>(
                &g_t_sq[colBase + ncol + 8 * i4]);
            const float4 tn1 = *reinterpret_cast<const float4*>(
                &g_t_sq[colBase + ncol + 8 * i4 + 4]);

#pragma unroll
            for (int mb2 = 0; mb2 < 4; mb2++) {
#pragma unroll
                for (int h = 0; h < 2; h++) {
                    const int r = mrow + mb2 * 16 + g + 8 * h;
                    const float srow = g_s_sq[rowBase + r];
                    float4 o0, o1;
                    o0.x = fmaf(-2.f, acc[mb2][0][2 * h + 0], srow + tn0.x);
                    o0.y = fmaf(-2.f, acc[mb2][0][2 * h + 1], srow + tn0.y);
                    o0.z = fmaf(-2.f, acc[mb2][1][2 * h + 0], srow + tn0.z);
                    o0.w = fmaf(-2.f, acc[mb2][1][2 * h + 1], srow + tn0.w);
                    o1.x = fmaf(-2.f, acc[mb2][2][2 * h + 0], srow + tn1.x);
                    o1.y = fmaf(-2.f, acc[mb2][2][2 * h + 1], srow + tn1.y);
                    o1.z = fmaf(-2.f, acc[mb2][3][2 * h + 0], srow + tn1.z);
                    o1.w = fmaf(-2.f, acc[mb2][3][2 * h + 1], srow + tn1.w);

                    float* dst = out + (size_t)(rowBase + r) * q
                               + colBase + ncol + 8 * i4;
                    *reinterpret_cast<float4*>(dst)     = o0;
                    *reinterpret_cast<float4*>(dst + 4) = o1;
                }
            }
        }
        __syncthreads();   // all reads of this buffer done before its reuse
    }
}

extern "C" void kernel_launch(void* const* d_in, const int* in_sizes, int n_in,
                              void* d_out, int out_size) {
    const float* s = (const float*)d_in[0];
    const float* t = (const float*)d_in[1];
    float* out = (float*)d_out;

    const int n = in_sizes[0] / D;
    const int q = in_sizes[1] / D;

    dim3 pgrid((((n > q) ? n : q) + 63) / 64, 2);
    prep_kernel<<<pgrid, 256>>>(s, t, n, q);

    const int tiles = (n / BM) * (q / BN);
    int ncta = 296;                       // 2 CTAs/SM x 148 SMs
    if (tiles < ncta) ncta = tiles;

    cudaFuncSetAttribute(dist_bf16_kernel,
                         cudaFuncAttributeMaxDynamicSharedMemorySize, 2 * BUF_BYTES);
    dist_bf16_kernel<<<ncta, 256, 2 * BUF_BYTES>>>(out, n, q, ncta);
}